// round 2
// baseline (speedup 1.0000x reference)
#include <cuda_runtime.h>
#include <cuda_fp16.h>
#include <cstdint>

#define NROW 12288
#define INF  128
#define OUTF 64
#define LOG2E 1.44269504088896341f
#define NCHUNK 8
#define CHUNK_TILES 12          // 12*128 = 1536 cols per chunk
#define NITILE (NROW / 128)     // 96
#define NUNITS (NITILE * NCHUNK) // 768
#define GRID 148
#define AS_STRIDE 136
#define BS_STRIDE 136

// ---------------- device scratch ----------------
__device__ float  g_wh1[NROW];
__device__ float  g_wh2[NROW];
__device__ float  g_wh2max;
__device__ __half g_hT[OUTF * NROW];            // h transposed fp16 [f][j]
__device__ float  g_S[NCHUNK][NROW * 72];       // partial (E' @ [h|1|0]) per chunk

// ---------------- Kernel A: h = input@W, wh1/wh2, hT ----------------
__global__ void kA(const float* __restrict__ inp, const float* __restrict__ W,
                   const float* __restrict__ a) {
    __shared__ float in_s[4][INF];
    __shared__ float red1[8], red2[8];
    int tid = threadIdx.x;
    int i0 = blockIdx.x * 4;
    for (int e = tid; e < 4 * INF; e += 256)
        in_s[e >> 7][e & 127] = inp[(i0 + (e >> 7)) * INF + (e & 127)];
    __syncthreads();
    int f = tid & 63, r = tid >> 6;
    float acc = 0.f;
#pragma unroll 8
    for (int k = 0; k < INF; k++)
        acc = fmaf(in_s[r][k], W[k * OUTF + f], acc);
    int i = i0 + r;
    g_hT[f * NROW + i] = __float2half(acc);
    float p1 = acc * a[f];
    float p2 = acc * a[64 + f];
#pragma unroll
    for (int o = 16; o > 0; o >>= 1) {
        p1 += __shfl_xor_sync(~0u, p1, o);
        p2 += __shfl_xor_sync(~0u, p2, o);
    }
    int w = tid >> 5;
    if ((tid & 31) == 0) { red1[w] = p1; red2[w] = p2; }
    __syncthreads();
    if (tid < 4) {
        g_wh1[i0 + tid] = red1[2 * tid] + red1[2 * tid + 1];
        g_wh2[i0 + tid] = red2[2 * tid] + red2[2 * tid + 1];
    }
}

// ---------------- Kernel A2: global max of wh2 ----------------
__global__ void kMax() {
    __shared__ float red[8];
    int tid = threadIdx.x;
    float m = -1e30f;
    for (int i = tid; i < NROW; i += 256) m = fmaxf(m, g_wh2[i]);
#pragma unroll
    for (int o = 16; o > 0; o >>= 1) m = fmaxf(m, __shfl_xor_sync(~0u, m, o));
    if ((tid & 31) == 0) red[tid >> 5] = m;
    __syncthreads();
    if (tid == 0) {
        float mm = red[0];
#pragma unroll
        for (int w = 1; w < 8; w++) mm = fmaxf(mm, red[w]);
        g_wh2max = mm;
    }
}

// ---------------- helpers ----------------
__device__ __forceinline__ void cp_async16(uint32_t dst, const void* src) {
    asm volatile("cp.async.cg.shared.global [%0], [%1], 16;\n"
                 :: "r"(dst), "l"(src));
}

// ---------------- Kernel B: persistent fused mask+lrelu+exp + (E'@[h|1]) ----------------
// grid 148, 512 threads, 1 CTA/SM. Double-buffered cp.async adj tiles.
__global__ void __launch_bounds__(512, 1) kMain(const int* __restrict__ adj) {
    extern __shared__ char smem_raw[];
    // layout: [0,128KB) adj double buffer; then A_s, B_s, wh1_s, m2_s
    __half* A_s = (__half*)(smem_raw + 131072);
    __half* B_s = (__half*)(smem_raw + 131072 + 128 * AS_STRIDE * 2);
    float* wh1_s = (float*)(smem_raw + 131072 + 128 * AS_STRIDE * 2 + 72 * BS_STRIDE * 2);
    float* m2_s = wh1_s + 128;

    int tid = threadIdx.x;
    int lane = tid & 31, w = tid >> 5;

    uint32_t smem_base = (uint32_t)__cvta_generic_to_shared(smem_raw);
    uint32_t A_base = smem_base + 131072;
    uint32_t B_base = A_base + 128 * AS_STRIDE * 2;

    // ones column (n=64) and zero pad rows (n=65..71) of B: written once
    uint32_t* B_su = (uint32_t*)B_s;
    for (int e = tid; e < 8 * 68; e += 512) {
        int rr = e / 68, c = e % 68;
        B_su[(64 + rr) * 68 + c] = (rr == 0) ? 0x3C003C00u : 0u;
    }

    const uint32_t* hTu = (const uint32_t*)g_hT;

    // cp.async mapping: thread covers 128B of the 64KB tile
    int cprow = tid >> 2;          // 0..127
    int cpseg = tid & 3;           // 0..3, each 32 ints

    // MMA geometry: warp pair (wm) owns 16 rows; halves split the 9 n-tiles 5/4
    int half = w & 1, wm = w >> 1;
    int nt0 = half * 5;
    int ntc = 5 - half;            // 5 or 4
    uint32_t a_ptr = A_base + (uint32_t)(((wm * 16 + (lane & 15)) * AS_STRIDE + ((lane >> 4) * 8)) * 2);
    int l15 = lane & 15;
    uint32_t b_ptr = B_base + (uint32_t)((((l15 & 7) * BS_STRIDE) + ((l15 >> 3) * 8)) * 2);

    const float wh2max = g_wh2max;

    for (int u = blockIdx.x; u < NUNITS; u += GRID) {
        int itile = u >> 3, chunk = u & 7;
        int i0 = itile * 128;
        int jbase = chunk * (CHUNK_TILES * 128);

        // prologue: async load tile 0 into buf 0
        {
            const int* src = adj + (long long)(i0 + cprow) * NROW + jbase + cpseg * 32;
            uint32_t dst = smem_base + (uint32_t)(tid * 128);
#pragma unroll
            for (int k = 0; k < 8; k++) cp_async16(dst + k * 16, src + k * 4);
            asm volatile("cp.async.commit_group;");
        }

        if (tid < 128) {
            float w1 = g_wh1[i0 + tid];
            float s = w1 + wh2max;
            float m = fmaxf(s, 0.2f * s);      // lrelu upper bound of row max
            wh1_s[tid] = w1;
            m2_s[tid] = m * LOG2E;
        }
        __syncthreads();

        // per-warp preload of this unit's 8 build rows
        float w1r[8], m2r[8];
#pragma unroll
        for (int rr = 0; rr < 8; rr++) {
            int row = w * 8 + rr;
            w1r[rr] = wh1_s[row];
            m2r[rr] = m2_s[row];
        }

        float acc[5][4];
#pragma unroll
        for (int nt = 0; nt < 5; nt++)
#pragma unroll
            for (int q = 0; q < 4; q++) acc[nt][q] = 0.f;

        for (int t = 0; t < CHUNK_TILES; t++) {
            int j0 = jbase + t * 128;
            // prefetch tile t+1 into the other buffer
            if (t + 1 < CHUNK_TILES) {
                const int* src = adj + (long long)(i0 + cprow) * NROW + j0 + 128 + cpseg * 32;
                uint32_t dst = smem_base + (uint32_t)(((t + 1) & 1) * 65536 + tid * 128);
#pragma unroll
                for (int k = 0; k < 8; k++) cp_async16(dst + k * 16, src + k * 4);
                asm volatile("cp.async.commit_group;");
                asm volatile("cp.async.wait_group 1;");
            } else {
                asm volatile("cp.async.wait_group 0;");
            }
            __syncthreads();   // adj(t) ready AND previous MMA done with A_s/B_s

            // build B_s rows 0..63 from hT (L2-resident, 1.5MB)
            {
                int j0h = j0 >> 1;
                for (int e = tid; e < 64 * 64; e += 512) {
                    int n = e >> 6, kp = e & 63;
                    B_su[n * 68 + kp] = hTu[n * (NROW / 2) + j0h + kp];
                }
            }
            // build A_s: warp w rows w*8..w*8+7, lane covers 4 j's
            {
                const int* abuf = (const int*)(smem_raw + (t & 1) * 65536);
                float4 wv = *(const float4*)(g_wh2 + j0 + lane * 4);
#pragma unroll
                for (int rr = 0; rr < 8; rr++) {
                    int row = w * 8 + rr;
                    int4 av = *(const int4*)(abuf + row * 128 + lane * 4);
                    float w1 = w1r[rr], m2 = m2r[rr];
                    float s0 = w1 + wv.x, s1 = w1 + wv.y, s2 = w1 + wv.z, s3 = w1 + wv.w;
                    // x = lrelu(s)*log2e - m2 = max(s*L - m2, 0.2*s*L - m2), masked -> -1e4
                    float x0 = fmaxf(fmaf(s0, LOG2E, -m2), fmaf(s0, 0.2f * LOG2E, -m2));
                    float x1 = fmaxf(fmaf(s1, LOG2E, -m2), fmaf(s1, 0.2f * LOG2E, -m2));
                    float x2 = fmaxf(fmaf(s2, LOG2E, -m2), fmaf(s2, 0.2f * LOG2E, -m2));
                    float x3 = fmaxf(fmaf(s3, LOG2E, -m2), fmaf(s3, 0.2f * LOG2E, -m2));
                    x0 = av.x ? x0 : -1e4f;
                    x1 = av.y ? x1 : -1e4f;
                    x2 = av.z ? x2 : -1e4f;
                    x3 = av.w ? x3 : -1e4f;
                    __half2 p01 = __floats2half2_rn(x0, x1);
                    __half2 p23 = __floats2half2_rn(x2, x3);
                    uint32_t u01 = *(uint32_t*)&p01;
                    uint32_t u23 = *(uint32_t*)&p23;
                    uint32_t e01, e23;
                    asm("ex2.approx.f16x2 %0, %1;" : "=r"(e01) : "r"(u01));
                    asm("ex2.approx.f16x2 %0, %1;" : "=r"(e23) : "r"(u23));
                    uint2 pk; pk.x = e01; pk.y = e23;
                    *(uint2*)(A_s + row * AS_STRIDE + lane * 4) = pk;
                }
            }
            __syncthreads();

            // MMA: warp pair wm covers rows wm*16..+15; halves split n-tiles
#pragma unroll
            for (int ks = 0; ks < 8; ks++) {
                uint32_t a0, a1, a2, a3;
                uint32_t aaddr = a_ptr + (uint32_t)(ks * 16 * 2);
                asm volatile("ldmatrix.sync.aligned.m8n8.x4.shared.b16 {%0,%1,%2,%3}, [%4];"
                             : "=r"(a0), "=r"(a1), "=r"(a2), "=r"(a3) : "r"(aaddr));
#pragma unroll
                for (int nt = 0; nt < 5; nt++) {
                    if (nt >= ntc) break;
                    uint32_t b0, b1;
                    uint32_t baddr = b_ptr + (uint32_t)((((nt0 + nt) * 8) * BS_STRIDE + ks * 16) * 2);
                    asm volatile("ldmatrix.sync.aligned.m8n8.x2.shared.b16 {%0,%1}, [%2];"
                                 : "=r"(b0), "=r"(b1) : "r"(baddr));
                    asm volatile("mma.sync.aligned.m16n8k16.row.col.f32.f16.f16.f32 "
                                 "{%0,%1,%2,%3}, {%4,%5,%6,%7}, {%8,%9}, {%0,%1,%2,%3};"
                                 : "+f"(acc[nt][0]), "+f"(acc[nt][1]), "+f"(acc[nt][2]), "+f"(acc[nt][3])
                                 : "r"(a0), "r"(a1), "r"(a2), "r"(a3), "r"(b0), "r"(b1));
                }
            }
        }

        // write out partial S for this unit
        int g = lane >> 2, tq = lane & 3;
        float* Sp = g_S[chunk];
#pragma unroll
        for (int nt = 0; nt < 5; nt++) {
            if (nt >= ntc) break;
            int col = (nt0 + nt) * 8 + tq * 2;
            int row0 = i0 + wm * 16 + g;
            *(float2*)(Sp + row0 * 72 + col)       = make_float2(acc[nt][0], acc[nt][1]);
            *(float2*)(Sp + (row0 + 8) * 72 + col) = make_float2(acc[nt][2], acc[nt][3]);
        }
        __syncthreads();  // partials written before next unit reuses smem
    }
}

// ---------------- Kernel C: reduce splits, normalize + ELU ----------------
__global__ void kEpi(float* __restrict__ out) {
    int idx = blockIdx.x * 256 + threadIdx.x;   // NROW*64 total
    int i = idx >> 6, f = idx & 63;
    float l = 0.f, v = 0.f;
#pragma unroll
    for (int c = 0; c < NCHUNK; c++) {
        l += g_S[c][i * 72 + 64];
        v += g_S[c][i * 72 + f];
    }
    v /= l;
    out[idx] = v > 0.f ? v : expm1f(v);
}

// ---------------- launch ----------------
extern "C" void kernel_launch(void* const* d_in, const int* in_sizes, int n_in,
                              void* d_out, int out_size) {
    (void)in_sizes; (void)n_in; (void)out_size;
    const float* inp = (const float*)d_in[0];
    const int*   adj = (const int*)d_in[1];
    const float* W   = (const float*)d_in[2];
    const float* a   = (const float*)d_in[3];

    const int smem_bytes = 131072 + 128 * AS_STRIDE * 2 + 72 * BS_STRIDE * 2 + 256 * 4; // 186496
    cudaFuncSetAttribute(kMain, cudaFuncAttributeMaxDynamicSharedMemorySize, smem_bytes);

    kA<<<NROW / 4, 256>>>(inp, W, a);
    kMax<<<1, 256>>>();
    kMain<<<GRID, 512, smem_bytes>>>(adj);
    kEpi<<<NROW * OUTF / 256, 256>>>((float*)d_out);
}

// round 5
// speedup vs baseline: 1.9860x; 1.9860x over previous
#include <cuda_runtime.h>
#include <cuda_fp16.h>
#include <cstdint>

#define NROW 12288
#define INF  128
#define OUTF 64
#define LOG2E 1.44269504088896341f
#define NCHUNK 6
#define CHUNK_TILES 16            // 16*128 = 2048 cols per chunk
#define NITILE (NROW / 128)       // 96
#define NUNITS (NITILE * NCHUNK)  // 576
#define GRID 148
#define AS 136                    // halfs per A row (128 + 8 pad)
#define BS 136
#define A_SZ (128 * AS * 2)       // 34816
#define B_SZ (64 * BS * 2)        // 17408
#define A_OFF0 0
#define A_OFF1 A_SZ
#define B_OFF0 (2 * A_SZ)
#define B_OFF1 (2 * A_SZ + B_SZ)
#define SMEM_BYTES (2 * A_SZ + 2 * B_SZ)   // 104448

// ---------------- device scratch ----------------
__device__ float  g_wh1[NROW];
__device__ float  g_wh2[NROW];
__device__ float  g_wh2max;
__device__ __half g_hT[OUTF * NROW];          // h transposed fp16 [f][j]
__device__ float  g_S[NCHUNK][NROW * OUTF];   // partial E'@h per chunk
__device__ float  g_L[NCHUNK][NROW];          // partial row sums per chunk

// ---------------- Kernel A: h = input@W, wh1/wh2, hT ----------------
__global__ void kA(const float* __restrict__ inp, const float* __restrict__ W,
                   const float* __restrict__ a) {
    __shared__ float in_s[4][INF];
    __shared__ float red1[8], red2[8];
    int tid = threadIdx.x;
    int i0 = blockIdx.x * 4;
    for (int e = tid; e < 4 * INF; e += 256)
        in_s[e >> 7][e & 127] = inp[(i0 + (e >> 7)) * INF + (e & 127)];
    __syncthreads();
    int f = tid & 63, r = tid >> 6;
    float acc = 0.f;
#pragma unroll 8
    for (int k = 0; k < INF; k++)
        acc = fmaf(in_s[r][k], W[k * OUTF + f], acc);
    int i = i0 + r;
    g_hT[f * NROW + i] = __float2half(acc);
    float p1 = acc * a[f];
    float p2 = acc * a[64 + f];
#pragma unroll
    for (int o = 16; o > 0; o >>= 1) {
        p1 += __shfl_xor_sync(~0u, p1, o);
        p2 += __shfl_xor_sync(~0u, p2, o);
    }
    int w = tid >> 5;
    if ((tid & 31) == 0) { red1[w] = p1; red2[w] = p2; }
    __syncthreads();
    if (tid < 4) {
        g_wh1[i0 + tid] = red1[2 * tid] + red1[2 * tid + 1];
        g_wh2[i0 + tid] = red2[2 * tid] + red2[2 * tid + 1];
    }
}

// ---------------- Kernel A2: global max of wh2 ----------------
__global__ void kMax() {
    __shared__ float red[8];
    int tid = threadIdx.x;
    float m = -1e30f;
    for (int i = tid; i < NROW; i += 256) m = fmaxf(m, g_wh2[i]);
#pragma unroll
    for (int o = 16; o > 0; o >>= 1) m = fmaxf(m, __shfl_xor_sync(~0u, m, o));
    if ((tid & 31) == 0) red[tid >> 5] = m;
    __syncthreads();
    if (tid == 0) {
        float mm = red[0];
#pragma unroll
        for (int w = 1; w < 8; w++) mm = fmaxf(mm, red[w]);
        g_wh2max = mm;
    }
}

// pad launches so ncu's "-s 5 -c 1" capture lands on kMain (6th launch)
__global__ void kPad() {}

// ---------------- Kernel B: persistent warp-specialized pipeline ----------------
// 384 threads: warps 0-7 build (adj stream + E' + B tile), warps 8-11 MMA.
__global__ void __launch_bounds__(384, 1) kMain(const int* __restrict__ adj) {
    extern __shared__ char smem[];
    uint32_t sb = (uint32_t)__cvta_generic_to_shared(smem);
    int tid = threadIdx.x, lane = tid & 31, w = tid >> 5;
    const float wh2max = g_wh2max;
    const uint32_t* hTu = (const uint32_t*)g_hT;

    if (w < 8) {
        // ================= builders =================
        int rowbase = w * 16;
        uint32_t abuf_part = (uint32_t)(rowbase * AS * 2 + lane * 8);
        int gt = 0;
        for (int u = blockIdx.x; u < NUNITS; u += GRID) {
            int itile = u / NCHUNK, chunk = u % NCHUNK;
            int i0 = itile * 128;
            int jbase = chunk * (CHUNK_TILES * 128);

            float w1r[16], m2r[16], racc[16];
#pragma unroll
            for (int rr = 0; rr < 16; rr++) {
                float w1 = g_wh1[i0 + rowbase + rr];
                float s = w1 + wh2max;
                float m = fmaxf(s, 0.2f * s);     // lrelu upper bound of row max
                w1r[rr] = w1;
                m2r[rr] = m * LOG2E;
                racc[rr] = 0.f;
            }

            for (int t = 0; t < CHUNK_TILES; t++) {
                int b = t & 1;
                int j0 = jbase + t * 128;

                // issue all global loads BEFORE the buffer-empty wait
                const int* abase = adj + (long long)(i0 + rowbase) * NROW + j0 + lane * 4;
                int4 av[16];
#pragma unroll
                for (int rr = 0; rr < 16; rr++)
                    av[rr] = __ldcs((const int4*)(abase + (long long)rr * NROW));
                float4 wv = *(const float4*)(g_wh2 + j0 + lane * 4);
                uint32_t bwd[16];
                int j0h = j0 >> 1;
#pragma unroll
                for (int s = 0; s < 16; s++) {
                    int e = tid + s * 256;
                    bwd[s] = hTu[(e >> 6) * (NROW / 2) + j0h + (e & 63)];
                }

                if (gt >= 2) asm volatile("bar.sync %0, 384;" :: "r"(3 + b));

                uint32_t abuf = sb + (b ? A_OFF1 : A_OFF0) + abuf_part;
#pragma unroll
                for (int rr = 0; rr < 16; rr++) {
                    float w1 = w1r[rr], m2 = m2r[rr];
                    float s0 = w1 + wv.x, s1 = w1 + wv.y, s2 = w1 + wv.z, s3 = w1 + wv.w;
                    float x0 = fmaxf(fmaf(s0, LOG2E, -m2), fmaf(s0, 0.2f * LOG2E, -m2));
                    float x1 = fmaxf(fmaf(s1, LOG2E, -m2), fmaf(s1, 0.2f * LOG2E, -m2));
                    float x2 = fmaxf(fmaf(s2, LOG2E, -m2), fmaf(s2, 0.2f * LOG2E, -m2));
                    float x3 = fmaxf(fmaf(s3, LOG2E, -m2), fmaf(s3, 0.2f * LOG2E, -m2));
                    x0 = av[rr].x ? x0 : -1e4f;
                    x1 = av[rr].y ? x1 : -1e4f;
                    x2 = av[rr].z ? x2 : -1e4f;
                    x3 = av[rr].w ? x3 : -1e4f;
                    __half2 p01 = __floats2half2_rn(x0, x1);
                    __half2 p23 = __floats2half2_rn(x2, x3);
                    uint32_t u01 = *(uint32_t*)&p01;
                    uint32_t u23 = *(uint32_t*)&p23;
                    uint32_t e01, e23;
                    asm("ex2.approx.f16x2 %0, %1;" : "=r"(e01) : "r"(u01));
                    asm("ex2.approx.f16x2 %0, %1;" : "=r"(e23) : "r"(u23));
                    float2 f01 = __half22float2(*(__half2*)&e01);
                    float2 f23 = __half22float2(*(__half2*)&e23);
                    racc[rr] += (f01.x + f01.y) + (f23.x + f23.y);
                    asm volatile("st.shared.v2.b32 [%0], {%1,%2};"
                                 :: "r"(abuf + (uint32_t)(rr * AS * 2)), "r"(e01), "r"(e23));
                }
                uint32_t bbuf = sb + (b ? B_OFF1 : B_OFF0);
#pragma unroll
                for (int s = 0; s < 16; s++) {
                    int e = tid + s * 256;
                    uint32_t addr = bbuf + (uint32_t)((e >> 6) * BS * 2 + (e & 63) * 4);
                    asm volatile("st.shared.b32 [%0], %1;" :: "r"(addr), "r"(bwd[s]));
                }
                asm volatile("membar.cta;" ::: "memory");
                asm volatile("bar.arrive %0, 384;" :: "r"(1 + b));
                gt++;
            }

            // row-sum reduce + store
#pragma unroll
            for (int rr = 0; rr < 16; rr++) {
                float v = racc[rr];
#pragma unroll
                for (int o = 16; o > 0; o >>= 1) v += __shfl_xor_sync(~0u, v, o);
                if (lane == rr) g_L[chunk][i0 + rowbase + rr] = v;
            }
        }
    } else {
        // ================= MMA warps =================
        int mw = w - 8;                 // 0..3, rows mw*32..+31
        int l15 = lane & 15;
        uint32_t a_off = (uint32_t)(((mw * 32 + l15) * AS + (lane >> 4) * 8) * 2);
        uint32_t b_off = (uint32_t)(((l15 & 7) * BS + (l15 >> 3) * 8) * 2);

        for (int u = blockIdx.x; u < NUNITS; u += GRID) {
            int itile = u / NCHUNK, chunk = u % NCHUNK;
            int i0 = itile * 128;

            float acc[2][8][4];
#pragma unroll
            for (int mt = 0; mt < 2; mt++)
#pragma unroll
                for (int nt = 0; nt < 8; nt++)
#pragma unroll
                    for (int q = 0; q < 4; q++) acc[mt][nt][q] = 0.f;

            for (int t = 0; t < CHUNK_TILES; t++) {
                int b = t & 1;
                asm volatile("bar.sync %0, 384;" :: "r"(1 + b));
                uint32_t Ab = sb + (b ? A_OFF1 : A_OFF0) + a_off;
                uint32_t Bb = sb + (b ? B_OFF1 : B_OFF0) + b_off;
#pragma unroll
                for (int ks = 0; ks < 8; ks++) {
                    uint32_t a0, a1, a2, a3, a4, a5, a6, a7;
                    asm volatile("ldmatrix.sync.aligned.m8n8.x4.shared.b16 {%0,%1,%2,%3}, [%4];"
                                 : "=r"(a0), "=r"(a1), "=r"(a2), "=r"(a3)
                                 : "r"(Ab + (uint32_t)(ks * 32)));
                    asm volatile("ldmatrix.sync.aligned.m8n8.x4.shared.b16 {%0,%1,%2,%3}, [%4];"
                                 : "=r"(a4), "=r"(a5), "=r"(a6), "=r"(a7)
                                 : "r"(Ab + (uint32_t)(16 * AS * 2 + ks * 32)));
#pragma unroll
                    for (int nt = 0; nt < 8; nt++) {
                        uint32_t b0, b1;
                        asm volatile("ldmatrix.sync.aligned.m8n8.x2.shared.b16 {%0,%1}, [%2];"
                                     : "=r"(b0), "=r"(b1)
                                     : "r"(Bb + (uint32_t)((nt * 8 * BS + ks * 16) * 2)));
                        asm volatile("mma.sync.aligned.m16n8k16.row.col.f32.f16.f16.f32 "
                                     "{%0,%1,%2,%3}, {%4,%5,%6,%7}, {%8,%9}, {%0,%1,%2,%3};"
                                     : "+f"(acc[0][nt][0]), "+f"(acc[0][nt][1]),
                                       "+f"(acc[0][nt][2]), "+f"(acc[0][nt][3])
                                     : "r"(a0), "r"(a1), "r"(a2), "r"(a3), "r"(b0), "r"(b1));
                        asm volatile("mma.sync.aligned.m16n8k16.row.col.f32.f16.f16.f32 "
                                     "{%0,%1,%2,%3}, {%4,%5,%6,%7}, {%8,%9}, {%0,%1,%2,%3};"
                                     : "+f"(acc[1][nt][0]), "+f"(acc[1][nt][1]),
                                       "+f"(acc[1][nt][2]), "+f"(acc[1][nt][3])
                                     : "r"(a4), "r"(a5), "r"(a6), "r"(a7), "r"(b0), "r"(b1));
                    }
                }
                asm volatile("bar.arrive %0, 384;" :: "r"(3 + b));
            }

            // unit epilogue: dump accumulators
            int g = lane >> 2, tq = lane & 3;
            float* Sp = g_S[chunk];
#pragma unroll
            for (int mt = 0; mt < 2; mt++)
#pragma unroll
                for (int nt = 0; nt < 8; nt++) {
                    int row0 = i0 + mw * 32 + mt * 16 + g;
                    int col = nt * 8 + tq * 2;
                    *(float2*)(Sp + row0 * OUTF + col) =
                        make_float2(acc[mt][nt][0], acc[mt][nt][1]);
                    *(float2*)(Sp + (row0 + 8) * OUTF + col) =
                        make_float2(acc[mt][nt][2], acc[mt][nt][3]);
                }
        }
    }
}

// ---------------- Kernel C: reduce chunks, normalize + ELU ----------------
__global__ void kEpi(float* __restrict__ out) {
    int idx = blockIdx.x * 256 + threadIdx.x;   // NROW*64
    int i = idx >> 6, f = idx & 63;
    float l = 0.f, v = 0.f;
#pragma unroll
    for (int c = 0; c < NCHUNK; c++) {
        l += g_L[c][i];
        v += g_S[c][i * OUTF + f];
    }
    v /= l;
    out[idx] = v > 0.f ? v : expm1f(v);
}

// ---------------- launch ----------------
extern "C" void kernel_launch(void* const* d_in, const int* in_sizes, int n_in,
                              void* d_out, int out_size) {
    (void)in_sizes; (void)n_in; (void)out_size;
    const float* inp = (const float*)d_in[0];
    const int*   adj = (const int*)d_in[1];
    const float* W   = (const float*)d_in[2];
    const float* a   = (const float*)d_in[3];

    cudaFuncSetAttribute(kMain, cudaFuncAttributeMaxDynamicSharedMemorySize, SMEM_BYTES);

    kA<<<NROW / 4, 256>>>(inp, W, a);        // launch 1
    kMax<<<1, 256>>>();                      // launch 2
    kPad<<<1, 32>>>();                       // launch 3
    kPad<<<1, 32>>>();                       // launch 4
    kPad<<<1, 32>>>();                       // launch 5
    kMain<<<GRID, 384, SMEM_BYTES>>>(adj);   // launch 6  <- ncu -s 5 -c 1 captures this
    kEpi<<<NROW * OUTF / 256, 256>>>((float*)d_out);
}